// round 15
// baseline (speedup 1.0000x reference)
#include <cuda_runtime.h>
#include <cuda_bf16.h>
#include <cuda_fp16.h>
#include <math.h>
#include <cstdint>

#define E_DIM 1024
#define SEQ   2048
#define BATCH 2
#define NHEAD 16
#define DK    64
#define MROWS (BATCH * SEQ)   // 4096

// ---------------------------------------------------------------------------
// Scratch (device globals; 16-bit storage, bits are fp16)
// ---------------------------------------------------------------------------
__device__ __nv_bfloat16 g_xf[MROWS * E_DIM];       // x fp16 single
__device__ __nv_bfloat16 g_wf[4][E_DIM * E_DIM];    // W fp16 single (q,k,v,o)
__device__ __nv_bfloat16 g_qf[MROWS * E_DIM];       // Q fp16 (scaled 1/8)
__device__ __nv_bfloat16 g_kf[MROWS * E_DIM];       // K fp16
__device__ __nv_bfloat16 g_vf[MROWS * E_DIM];       // V fp16
__device__ __nv_bfloat16 g_mf[MROWS * E_DIM];       // mix fp16

// ---------------------------------------------------------------------------
// Helpers
// ---------------------------------------------------------------------------
__device__ __forceinline__ uint32_t smem_to_u32(const void* p) {
    uint32_t a;
    asm("{ .reg .u64 t; cvta.to.shared.u64 t, %1; cvt.u32.u64 %0, t; }"
        : "=r"(a) : "l"(p));
    return a;
}
#define SWZ(o) ((o) ^ (((o) >> 3) & 0x70))

#define LDMATRIX_X4(r0, r1, r2, r3, addr) \
    asm volatile("ldmatrix.sync.aligned.m8n8.x4.shared.b16 {%0,%1,%2,%3}, [%4];" \
                 : "=r"(r0), "=r"(r1), "=r"(r2), "=r"(r3) : "r"(addr))

#define LDMATRIX_X4_T(r0, r1, r2, r3, addr) \
    asm volatile("ldmatrix.sync.aligned.m8n8.x4.trans.shared.b16 {%0,%1,%2,%3}, [%4];" \
                 : "=r"(r0), "=r"(r1), "=r"(r2), "=r"(r3) : "r"(addr))

#define MMA_F16(d, a, b) \
    asm volatile("mma.sync.aligned.m16n8k16.row.col.f32.f16.f16.f32 " \
                 "{%0,%1,%2,%3}, {%4,%5,%6,%7}, {%8,%9}, {%0,%1,%2,%3};" \
                 : "+f"((d)[0]), "+f"((d)[1]), "+f"((d)[2]), "+f"((d)[3]) \
                 : "r"((a)[0]), "r"((a)[1]), "r"((a)[2]), "r"((a)[3]), \
                   "r"((b)[0]), "r"((b)[1]))

#define CP_ASYNC16(s, g) \
    asm volatile("cp.async.cg.shared.global [%0], [%1], 16;" :: "r"(s), "l"(g))
#define CP_COMMIT() asm volatile("cp.async.commit_group;" ::: "memory")
#define CP_WAIT0() asm volatile("cp.async.wait_group 0;" ::: "memory")

// fp16 single pack
__device__ __forceinline__ unsigned pack_f16(float a, float b) {
    unsigned r;
    asm("cvt.rn.f16x2.f32 %0, %1, %2;" : "=r"(r) : "f"(b), "f"(a));
    return r;
}

// ---------------------------------------------------------------------------
// Prep: everything -> fp16 single
// ---------------------------------------------------------------------------
#define NX4 (MROWS * E_DIM / 4)     // 1M float4 (x)
#define NW4 (E_DIM * E_DIM / 4)     // 256K float4 (each weight)

__global__ __launch_bounds__(256) void prep_all(const float* __restrict__ x,
                                                const float* __restrict__ Wq,
                                                const float* __restrict__ Wk,
                                                const float* __restrict__ Wv,
                                                const float* __restrict__ Wo)
{
    int i = blockIdx.x * 256 + threadIdx.x;
    if (i < NX4) {
        float4 v = ((const float4*)x)[i];
        ((uint2*)g_xf)[i] = make_uint2(pack_f16(v.x, v.y), pack_f16(v.z, v.w));
    } else {
        int t = i - NX4;
        int w = t >> 18;            // / NW4
        int j = t & (NW4 - 1);
        const float* src = (w == 0) ? Wq : (w == 1) ? Wk : (w == 2) ? Wv : Wo;
        float4 v = ((const float4*)src)[j];
        ((uint2*)g_wf[w])[j] = make_uint2(pack_f16(v.x, v.y), pack_f16(v.z, v.w));
    }
}

// ---------------------------------------------------------------------------
// Pipelined GEMM: C[M,N] = A[M,K]*B[N,K]^T.  fp16 x fp16 single, 1 pass,
// fp32 acc. CTA 128x128 (128 threads, 4 warps of 64m x 64n), BK=64,
// 2-stage cp.async, one sync per kt.
// Stage = A 16KB + B 16KB = 32KB; 2 stages 64KB -> 2 CTAs/SM.
// outfmt: 0 = fp32, 3 = fp16 single (scaled)
// ---------------------------------------------------------------------------
#define GS_A   0
#define GS_B   16384
#define GSTAGE 32768
#define G_SMEM (2 * GSTAGE)
#define NKT (E_DIM / 64)   // 16

__device__ __forceinline__ void gemm_mma_body(const __nv_bfloat16* __restrict__ Af,
                                              const __nv_bfloat16* __restrict__ Bf,
                                              float* __restrict__ Cf,
                                              __nv_bfloat16* __restrict__ Ch,
                                              float scale, int outfmt)
{
    extern __shared__ __align__(1024) char sm[];
    const uint32_t smb = smem_to_u32(sm);
    const int tid  = threadIdx.x;
    const int w    = tid >> 5;
    const int lane = tid & 31;
    const int bm   = blockIdx.y;
    const int bn   = blockIdx.x;
    const int m0w  = (w & 1) * 64;
    const int n0w  = (w >> 1) * 64;

    float acc[4][8][4];
#pragma unroll
    for (int mt = 0; mt < 4; mt++)
#pragma unroll
        for (int nt = 0; nt < 8; nt++)
#pragma unroll
            for (int j = 0; j < 4; j++) acc[mt][nt][j] = 0.f;

    const int chunk = tid & 7;
    const int rbase = tid >> 3;          // 0..15
    const int ccol  = chunk * 8;         // element col within BK=64
    uint32_t sofs[8];
#pragma unroll
    for (int p = 0; p < 8; p++)
        sofs[p] = SWZ((uint32_t)((rbase + 16 * p) * 128 + chunk * 16));

    auto issue = [&](int kt, int st) {
        const uint32_t sb = smb + (uint32_t)st * GSTAGE;
        const int col = kt * 64 + ccol;
#pragma unroll
        for (int p = 0; p < 8; p++) {
            size_t ga = (size_t)(bm * 128 + rbase + 16 * p) * E_DIM + col;
            size_t gb = (size_t)(bn * 128 + rbase + 16 * p) * E_DIM + col;
            CP_ASYNC16(sb + GS_A + sofs[p], Af + ga);
            CP_ASYNC16(sb + GS_B + sofs[p], Bf + gb);
        }
        CP_COMMIT();
    };

    issue(0, 0);

    const int a_r   = (lane & 7) + ((lane >> 3) & 1) * 8;
    const int a_c16 = lane >> 4;
    const int b_r   = (lane & 7) + ((lane >> 4) & 1) * 8;
    const int b_c16 = (lane >> 3) & 1;

    for (int kt = 0; kt < NKT; kt++) {
        CP_WAIT0();
        __syncthreads();
        const uint32_t sb = smb + (uint32_t)(kt & 1) * GSTAGE;

        if (kt + 1 < NKT) issue(kt + 1, (kt + 1) & 1);

#pragma unroll
        for (int ks = 0; ks < 4; ks++) {
            uint32_t bf2[8][2];
#pragma unroll
            for (int ntp = 0; ntp < 4; ntp++) {
                int nrow = n0w + ntp * 16 + b_r;
                uint32_t off = SWZ((uint32_t)(nrow * 128 + ks * 32 + b_c16 * 16));
                LDMATRIX_X4(bf2[2 * ntp][0], bf2[2 * ntp][1],
                            bf2[2 * ntp + 1][0], bf2[2 * ntp + 1][1], sb + GS_B + off);
            }
#pragma unroll
            for (int mt = 0; mt < 4; mt++) {
                uint32_t af[4];
                int row = m0w + mt * 16 + a_r;
                uint32_t off = SWZ((uint32_t)(row * 128 + ks * 32 + a_c16 * 16));
                LDMATRIX_X4(af[0], af[1], af[2], af[3], sb + GS_A + off);
#pragma unroll
                for (int nt = 0; nt < 8; nt++)
                    MMA_F16(acc[mt][nt], af, bf2[nt]);
            }
        }
    }

#pragma unroll
    for (int mt = 0; mt < 4; mt++) {
        size_t m = (size_t)(bm * 128 + m0w + mt * 16 + (lane >> 2));
#pragma unroll
        for (int nt = 0; nt < 8; nt++) {
            size_t n = (size_t)(bn * 128 + n0w + nt * 8 + (lane & 3) * 2);
            if (outfmt == 0) {
                float* p = Cf + m * E_DIM + n;
                *(float2*)p = make_float2(acc[mt][nt][0], acc[mt][nt][1]);
                *(float2*)(p + (size_t)8 * E_DIM) = make_float2(acc[mt][nt][2], acc[mt][nt][3]);
            } else {
                *(unsigned*)(Ch + m * E_DIM + n) =
                    pack_f16(acc[mt][nt][0] * scale, acc[mt][nt][1] * scale);
                *(unsigned*)(Ch + (m + 8) * E_DIM + n) =
                    pack_f16(acc[mt][nt][2] * scale, acc[mt][nt][3] * scale);
            }
        }
    }
}

__global__ __launch_bounds__(128, 2) void qkv_gemm_mma()
{
    int z = blockIdx.z;
    __nv_bfloat16* C = (z == 0) ? g_qf : (z == 1) ? g_kf : g_vf;
    float scale = (z == 0) ? 0.125f : 1.0f;   // fold 1/sqrt(dk) into Q
    gemm_mma_body(g_xf, g_wf[z], nullptr, C, scale, 3);
}

__global__ __launch_bounds__(128, 2) void out_gemm_mma(float* __restrict__ C)
{
    gemm_mma_body(g_mf, g_wf[3], C, nullptr, 1.0f, 0);
}

// ---------------------------------------------------------------------------
// Flash attention, all single fp16, 1-pass QK and 1-pass PV. (R12 version)
// Per CTA: 128 q rows of one (b,h), 128 threads, 4 warps x 32 q-rows.
// Q fragments in REGISTERS (loaded once). KV tile 64, 2-stage cp.async,
// one sync/iter. smem = 2 x (K 8KB + V 8KB) = 32KB -> 2 CTAs/SM.
// ---------------------------------------------------------------------------
#define A_K   0
#define A_V   8192
#define ASTAGE 16384
#define ATTN_SMEM (2 * ASTAGE)
#define NKV (SEQ / 64)   // 32
#define QBLK 128

__global__ __launch_bounds__(128, 2) void attn_mma(const float* __restrict__ qp)
{
    extern __shared__ __align__(1024) char sm[];
    const uint32_t smb = smem_to_u32(sm);
    const int tid  = threadIdx.x;
    const int wid  = tid >> 5;
    const int lane = tid & 31;
    const int bh   = blockIdx.y;
    const int b    = bh >> 4;
    const int h    = bh & 15;
    const int qbase = blockIdx.x * QBLK;
    const int wq0   = wid * 32;
    const float cq  = cosf(qp[0] + qp[1]);

    const size_t bS = (size_t)b * SEQ;
    const int h64 = h * 64;

    const __nv_bfloat16* kg = g_kf + bS * E_DIM + h64;
    const __nv_bfloat16* vg = g_vf + bS * E_DIM + h64;
    const int chunk = tid & 7;
    const int crow  = tid >> 3;           // 0..15
    const int ccol  = chunk * 8;
    uint32_t sco[4];
#pragma unroll
    for (int p = 0; p < 4; p++)
        sco[p] = SWZ((uint32_t)((crow + 16 * p) * 128 + chunk * 16));

    auto issue_stage = [&](int it, int st) {
        const uint32_t sb = smb + (uint32_t)st * ASTAGE;
#pragma unroll
        for (int p = 0; p < 4; p++) {
            const size_t r = (size_t)(it * 64 + crow + 16 * p) * E_DIM + ccol;
            CP_ASYNC16(sb + A_K + sco[p], kg + r);
            CP_ASYNC16(sb + A_V + sco[p], vg + r);
        }
        CP_COMMIT();
    };

    issue_stage(0, 0);

    // ---- Q fragments in registers (fp16, pre-scaled), held all loop ----
    unsigned qf[2][4][4];   // [mt][ks][reg]
    {
#pragma unroll
        for (int mt = 0; mt < 2; mt++) {
            const size_t base = (bS + qbase + wq0 + mt * 16 + (lane >> 2)) * E_DIM
                                + h64 + (lane & 3) * 2;
            const __nv_bfloat16* qp_ = g_qf + base;
#pragma unroll
            for (int ks = 0; ks < 4; ks++) {
                qf[mt][ks][0] = *(const unsigned*)(qp_ + ks * 16);
                qf[mt][ks][1] = *(const unsigned*)(qp_ + 8 * E_DIM + ks * 16);
                qf[mt][ks][2] = *(const unsigned*)(qp_ + ks * 16 + 8);
                qf[mt][ks][3] = *(const unsigned*)(qp_ + 8 * E_DIM + ks * 16 + 8);
            }
        }
    }

    float mx[2][2], lsum[2][2];
    float oacc[2][8][4];
#pragma unroll
    for (int mt = 0; mt < 2; mt++) {
        mx[mt][0] = -1e30f; mx[mt][1] = -1e30f;
        lsum[mt][0] = 0.f;  lsum[mt][1] = 0.f;
#pragma unroll
        for (int nt = 0; nt < 8; nt++)
#pragma unroll
            for (int j = 0; j < 4; j++) oacc[mt][nt][j] = 0.f;
    }

    const int brow  = (lane & 7) + ((lane >> 4) & 1) * 8;
    const int bc16  = (lane >> 3) & 1;
    const int vrow  = lane & 15;
    const int vcs   = (lane >> 4) * 16;

    for (int it = 0; it < NKV; it++) {
        CP_WAIT0();
        __syncthreads();

        const uint32_t sb = smb + (uint32_t)(it & 1) * ASTAGE;

        if (it + 1 < NKV) issue_stage(it + 1, (it + 1) & 1);

        // ---- S = Q.K^T (fp16 x fp16, 1 pass), 2 m-tiles ----
        float sacc[2][8][4];
#pragma unroll
        for (int mt = 0; mt < 2; mt++)
#pragma unroll
            for (int nt = 0; nt < 8; nt++)
#pragma unroll
                for (int j = 0; j < 4; j++) sacc[mt][nt][j] = 0.f;

#pragma unroll
        for (int ks = 0; ks < 4; ks++) {
            unsigned kf2[8][2];
#pragma unroll
            for (int ntp = 0; ntp < 4; ntp++) {
                uint32_t off = SWZ((uint32_t)((ntp * 16 + brow) * 128 + ks * 32 + bc16 * 16));
                LDMATRIX_X4(kf2[2 * ntp][0], kf2[2 * ntp][1],
                            kf2[2 * ntp + 1][0], kf2[2 * ntp + 1][1], sb + A_K + off);
            }
#pragma unroll
            for (int mt = 0; mt < 2; mt++)
#pragma unroll
                for (int nt = 0; nt < 8; nt++)
                    MMA_F16(sacc[mt][nt], qf[mt][ks], kf2[nt]);
        }

        // ---- online softmax per m-tile ----
#pragma unroll
        for (int mt = 0; mt < 2; mt++) {
            float mn0 = mx[mt][0], mn1 = mx[mt][1];
#pragma unroll
            for (int nt = 0; nt < 8; nt++) {
                mn0 = fmaxf(mn0, fmaxf(sacc[mt][nt][0], sacc[mt][nt][1]));
                mn1 = fmaxf(mn1, fmaxf(sacc[mt][nt][2], sacc[mt][nt][3]));
            }
            mn0 = fmaxf(mn0, __shfl_xor_sync(0xffffffffu, mn0, 1));
            mn0 = fmaxf(mn0, __shfl_xor_sync(0xffffffffu, mn0, 2));
            mn1 = fmaxf(mn1, __shfl_xor_sync(0xffffffffu, mn1, 1));
            mn1 = fmaxf(mn1, __shfl_xor_sync(0xffffffffu, mn1, 2));
            float sc0 = __expf(mx[mt][0] - mn0);
            float sc1 = __expf(mx[mt][1] - mn1);
            mx[mt][0] = mn0; mx[mt][1] = mn1;
            float rs0 = 0.f, rs1 = 0.f;
#pragma unroll
            for (int nt = 0; nt < 8; nt++) {
                sacc[mt][nt][0] = __expf(sacc[mt][nt][0] - mn0); rs0 += sacc[mt][nt][0];
                sacc[mt][nt][1] = __expf(sacc[mt][nt][1] - mn0); rs0 += sacc[mt][nt][1];
                sacc[mt][nt][2] = __expf(sacc[mt][nt][2] - mn1); rs1 += sacc[mt][nt][2];
                sacc[mt][nt][3] = __expf(sacc[mt][nt][3] - mn1); rs1 += sacc[mt][nt][3];
            }
            rs0 += __shfl_xor_sync(0xffffffffu, rs0, 1);
            rs0 += __shfl_xor_sync(0xffffffffu, rs0, 2);
            rs1 += __shfl_xor_sync(0xffffffffu, rs1, 1);
            rs1 += __shfl_xor_sync(0xffffffffu, rs1, 2);
            lsum[mt][0] = lsum[mt][0] * sc0 + rs0;
            lsum[mt][1] = lsum[mt][1] * sc1 + rs1;
#pragma unroll
            for (int nt = 0; nt < 8; nt++) {
                oacc[mt][nt][0] *= sc0; oacc[mt][nt][1] *= sc0;
                oacc[mt][nt][2] *= sc1; oacc[mt][nt][3] *= sc1;
            }
        }

        // ---- O += P.V (fp16 x fp16, 1 pass) ----
#pragma unroll
        for (int j = 0; j < 4; j++) {
            unsigned vf2[8][2];
#pragma unroll
            for (int dp = 0; dp < 4; dp++) {
                uint32_t off = SWZ((uint32_t)((j * 16 + vrow) * 128 + dp * 32 + vcs));
                LDMATRIX_X4_T(vf2[2 * dp][0], vf2[2 * dp][1],
                              vf2[2 * dp + 1][0], vf2[2 * dp + 1][1], sb + A_V + off);
            }
#pragma unroll
            for (int mt = 0; mt < 2; mt++) {
                unsigned ph[4];
                ph[0] = pack_f16(sacc[mt][2 * j][0],     sacc[mt][2 * j][1]);
                ph[1] = pack_f16(sacc[mt][2 * j][2],     sacc[mt][2 * j][3]);
                ph[2] = pack_f16(sacc[mt][2 * j + 1][0], sacc[mt][2 * j + 1][1]);
                ph[3] = pack_f16(sacc[mt][2 * j + 1][2], sacc[mt][2 * j + 1][3]);
#pragma unroll
                for (int nt = 0; nt < 8; nt++)
                    MMA_F16(oacc[mt][nt], ph, vf2[nt]);
            }
        }
    }

    // ---- epilogue: normalize, +c on dk<4, write fp16 mix ----
    const bool adds = ((lane & 3) < 2);
#pragma unroll
    for (int mt = 0; mt < 2; mt++) {
        const float inv0 = 1.f / lsum[mt][0];
        const float inv1 = 1.f / lsum[mt][1];
        const size_t row0 = (bS + qbase + wq0 + mt * 16 + (lane >> 2)) * E_DIM
                            + h64 + (lane & 3) * 2;
        const size_t row1 = row0 + 8 * E_DIM;
#pragma unroll
        for (int nt = 0; nt < 8; nt++) {
            const float add = (nt == 0 && adds) ? cq : 0.f;
            *(unsigned*)(g_mf + row0 + nt * 8) =
                pack_f16(oacc[mt][nt][0] * inv0 + add, oacc[mt][nt][1] * inv0 + add);
            *(unsigned*)(g_mf + row1 + nt * 8) =
                pack_f16(oacc[mt][nt][2] * inv1 + add, oacc[mt][nt][3] * inv1 + add);
        }
    }
}

// ---------------------------------------------------------------------------
extern "C" void kernel_launch(void* const* d_in, const int* in_sizes, int n_in,
                              void* d_out, int out_size)
{
    const float* x  = (const float*)d_in[0];
    const float* Wq = (const float*)d_in[1];
    const float* Wk = (const float*)d_in[2];
    const float* Wv = (const float*)d_in[3];
    const float* Wo = (const float*)d_in[4];
    const float* qp = (const float*)d_in[5];
    float* out = (float*)d_out;

    cudaFuncSetAttribute(qkv_gemm_mma, cudaFuncAttributeMaxDynamicSharedMemorySize, G_SMEM);
    cudaFuncSetAttribute(out_gemm_mma, cudaFuncAttributeMaxDynamicSharedMemorySize, G_SMEM);
    cudaFuncSetAttribute(attn_mma,     cudaFuncAttributeMaxDynamicSharedMemorySize, ATTN_SMEM);

    const int NPREP = NX4 + 4 * NW4;   // 2M float4 units
    prep_all<<<(NPREP + 255) / 256, 256>>>(x, Wq, Wk, Wv, Wo);

    qkv_gemm_mma<<<dim3(8, 32, 3), 128, G_SMEM>>>();
    attn_mma<<<dim3(SEQ / QBLK, BATCH * NHEAD), 128, ATTN_SMEM>>>(qp);
    out_gemm_mma<<<dim3(8, 32), 128, G_SMEM>>>(out);
}

// round 16
// speedup vs baseline: 1.0232x; 1.0232x over previous
#include <cuda_runtime.h>
#include <cuda_bf16.h>
#include <cuda_fp16.h>
#include <math.h>
#include <cstdint>

#define E_DIM 1024
#define SEQ   2048
#define BATCH 2
#define NHEAD 16
#define DK    64
#define MROWS (BATCH * SEQ)   // 4096

// ---------------------------------------------------------------------------
// Scratch (device globals; 16-bit storage, bits are fp16)
// ---------------------------------------------------------------------------
__device__ __nv_bfloat16 g_xf[MROWS * E_DIM];       // x fp16 single
__device__ __nv_bfloat16 g_wf[4][E_DIM * E_DIM];    // W fp16 single (q,k,v,o)
__device__ __nv_bfloat16 g_qf[MROWS * E_DIM];       // Q fp16 (scaled 1/8)
__device__ __nv_bfloat16 g_kf[MROWS * E_DIM];       // K fp16
__device__ __nv_bfloat16 g_vf[MROWS * E_DIM];       // V fp16
__device__ __nv_bfloat16 g_mf[MROWS * E_DIM];       // mix fp16

// ---------------------------------------------------------------------------
// Helpers
// ---------------------------------------------------------------------------
__device__ __forceinline__ uint32_t smem_to_u32(const void* p) {
    uint32_t a;
    asm("{ .reg .u64 t; cvta.to.shared.u64 t, %1; cvt.u32.u64 %0, t; }"
        : "=r"(a) : "l"(p));
    return a;
}
#define SWZ(o) ((o) ^ (((o) >> 3) & 0x70))

#define LDMATRIX_X4(r0, r1, r2, r3, addr) \
    asm volatile("ldmatrix.sync.aligned.m8n8.x4.shared.b16 {%0,%1,%2,%3}, [%4];" \
                 : "=r"(r0), "=r"(r1), "=r"(r2), "=r"(r3) : "r"(addr))

#define LDMATRIX_X4_T(r0, r1, r2, r3, addr) \
    asm volatile("ldmatrix.sync.aligned.m8n8.x4.trans.shared.b16 {%0,%1,%2,%3}, [%4];" \
                 : "=r"(r0), "=r"(r1), "=r"(r2), "=r"(r3) : "r"(addr))

#define MMA_F16(d, a, b) \
    asm volatile("mma.sync.aligned.m16n8k16.row.col.f32.f16.f16.f32 " \
                 "{%0,%1,%2,%3}, {%4,%5,%6,%7}, {%8,%9}, {%0,%1,%2,%3};" \
                 : "+f"((d)[0]), "+f"((d)[1]), "+f"((d)[2]), "+f"((d)[3]) \
                 : "r"((a)[0]), "r"((a)[1]), "r"((a)[2]), "r"((a)[3]), \
                   "r"((b)[0]), "r"((b)[1]))

#define CP_ASYNC16(s, g) \
    asm volatile("cp.async.cg.shared.global [%0], [%1], 16;" :: "r"(s), "l"(g))
#define CP_COMMIT() asm volatile("cp.async.commit_group;" ::: "memory")
#define CP_WAIT0() asm volatile("cp.async.wait_group 0;" ::: "memory")

// fp16 single pack
__device__ __forceinline__ unsigned pack_f16(float a, float b) {
    unsigned r;
    asm("cvt.rn.f16x2.f32 %0, %1, %2;" : "=r"(r) : "f"(b), "f"(a));
    return r;
}

// ---------------------------------------------------------------------------
// Prep: everything -> fp16 single. 2 float4 per thread for MLP.
// ---------------------------------------------------------------------------
#define NX4 (MROWS * E_DIM / 4)     // 1M float4 (x)
#define NW4 (E_DIM * E_DIM / 4)     // 256K float4 (each weight)
#define NPREP4 (NX4 + 4 * NW4)      // 2M float4

__global__ __launch_bounds__(256) void prep_all(const float* __restrict__ x,
                                                const float* __restrict__ Wq,
                                                const float* __restrict__ Wk,
                                                const float* __restrict__ Wv,
                                                const float* __restrict__ Wo)
{
    int i0 = blockIdx.x * 512 + threadIdx.x;
#pragma unroll
    for (int u = 0; u < 2; u++) {
        int i = i0 + u * 256;
        if (i >= NPREP4) return;
        const float* src;
        __nv_bfloat16* dst;
        int j;
        if (i < NX4) {
            src = x; dst = g_xf; j = i;
        } else {
            int t = i - NX4;
            int w = t >> 18;            // / NW4
            j = t & (NW4 - 1);
            src = (w == 0) ? Wq : (w == 1) ? Wk : (w == 2) ? Wv : Wo;
            dst = g_wf[w];
        }
        float4 v = ((const float4*)src)[j];
        ((uint2*)dst)[j] = make_uint2(pack_f16(v.x, v.y), pack_f16(v.z, v.w));
    }
}

// ---------------------------------------------------------------------------
// QKV GEMM (R12 shape): CTA 128x64 (4 warps of 64m x 32n), BK=64,
// 2-stage cp.async, one sync per kt. Stage = A 16KB + B 8KB = 24KB; 48KB tot.
// 3 CTAs/SM. fp16 x fp16, 1 pass, fp32 acc, fp16 out (scaled).
// ---------------------------------------------------------------------------
#define QG_A   0
#define QG_B   16384
#define QGSTAGE 24576
#define QG_SMEM (2 * QGSTAGE)
#define NKT (E_DIM / 64)   // 16

__global__ __launch_bounds__(128, 3) void qkv_gemm_mma()
{
    extern __shared__ __align__(1024) char sm[];
    const uint32_t smb = smem_to_u32(sm);
    const int z = blockIdx.z;
    const __nv_bfloat16* Af = g_xf;
    const __nv_bfloat16* Bf = g_wf[z];
    __nv_bfloat16* Ch = (z == 0) ? g_qf : (z == 1) ? g_kf : g_vf;
    const float scale = (z == 0) ? 0.125f : 1.0f;

    const int tid  = threadIdx.x;
    const int w    = tid >> 5;
    const int lane = tid & 31;
    const int bm   = blockIdx.y;
    const int bn   = blockIdx.x;
    const int m0w  = (w & 1) * 64;
    const int n0w  = (w >> 1) * 32;

    float acc[4][4][4];
#pragma unroll
    for (int mt = 0; mt < 4; mt++)
#pragma unroll
        for (int nt = 0; nt < 4; nt++)
#pragma unroll
            for (int j = 0; j < 4; j++) acc[mt][nt][j] = 0.f;

    const int chunk = tid & 7;
    const int rbase = tid >> 3;
    const int ccol  = chunk * 8;
    uint32_t sofs[8];
#pragma unroll
    for (int p = 0; p < 8; p++)
        sofs[p] = SWZ((uint32_t)((rbase + 16 * p) * 128 + chunk * 16));

    auto issue = [&](int kt, int st) {
        const uint32_t sb = smb + (uint32_t)st * QGSTAGE;
        const int col = kt * 64 + ccol;
#pragma unroll
        for (int p = 0; p < 8; p++)
            CP_ASYNC16(sb + QG_A + sofs[p],
                       Af + (size_t)(bm * 128 + rbase + 16 * p) * E_DIM + col);
#pragma unroll
        for (int p = 0; p < 4; p++)
            CP_ASYNC16(sb + QG_B + sofs[p],
                       Bf + (size_t)(bn * 64 + rbase + 16 * p) * E_DIM + col);
        CP_COMMIT();
    };

    issue(0, 0);

    const int a_r   = (lane & 7) + ((lane >> 3) & 1) * 8;
    const int a_c16 = lane >> 4;
    const int b_r   = (lane & 7) + ((lane >> 4) & 1) * 8;
    const int b_c16 = (lane >> 3) & 1;

    for (int kt = 0; kt < NKT; kt++) {
        CP_WAIT0();
        __syncthreads();
        const uint32_t sb = smb + (uint32_t)(kt & 1) * QGSTAGE;

        if (kt + 1 < NKT) issue(kt + 1, (kt + 1) & 1);

#pragma unroll
        for (int ks = 0; ks < 4; ks++) {
            uint32_t bf2[4][2];
#pragma unroll
            for (int ntp = 0; ntp < 2; ntp++) {
                int nrow = n0w + ntp * 16 + b_r;
                uint32_t off = SWZ((uint32_t)(nrow * 128 + ks * 32 + b_c16 * 16));
                LDMATRIX_X4(bf2[2 * ntp][0], bf2[2 * ntp][1],
                            bf2[2 * ntp + 1][0], bf2[2 * ntp + 1][1], sb + QG_B + off);
            }
#pragma unroll
            for (int mt = 0; mt < 4; mt++) {
                uint32_t af[4];
                int row = m0w + mt * 16 + a_r;
                uint32_t off = SWZ((uint32_t)(row * 128 + ks * 32 + a_c16 * 16));
                LDMATRIX_X4(af[0], af[1], af[2], af[3], sb + QG_A + off);
#pragma unroll
                for (int nt = 0; nt < 4; nt++)
                    MMA_F16(acc[mt][nt], af, bf2[nt]);
            }
        }
    }

#pragma unroll
    for (int mt = 0; mt < 4; mt++) {
        size_t m = (size_t)(bm * 128 + m0w + mt * 16 + (lane >> 2));
#pragma unroll
        for (int nt = 0; nt < 4; nt++) {
            size_t n = (size_t)(bn * 64 + n0w + nt * 8 + (lane & 3) * 2);
            *(unsigned*)(Ch + m * E_DIM + n) =
                pack_f16(acc[mt][nt][0] * scale, acc[mt][nt][1] * scale);
            *(unsigned*)(Ch + (m + 8) * E_DIM + n) =
                pack_f16(acc[mt][nt][2] * scale, acc[mt][nt][3] * scale);
        }
    }
}

// ---------------------------------------------------------------------------
// OUT GEMM (R13 shape): CTA 128x128 (4 warps of 64m x 64n), BK=64,
// 2-stage cp.async. Stage = 32KB; 64KB total. 2 CTAs/SM. fp32 out.
// ---------------------------------------------------------------------------
#define OG_A   0
#define OG_B   16384
#define OGSTAGE 32768
#define OG_SMEM (2 * OGSTAGE)

__global__ __launch_bounds__(128, 2) void out_gemm_mma(float* __restrict__ Cf)
{
    extern __shared__ __align__(1024) char sm[];
    const uint32_t smb = smem_to_u32(sm);
    const __nv_bfloat16* Af = g_mf;
    const __nv_bfloat16* Bf = g_wf[3];

    const int tid  = threadIdx.x;
    const int w    = tid >> 5;
    const int lane = tid & 31;
    const int bm   = blockIdx.y;
    const int bn   = blockIdx.x;
    const int m0w  = (w & 1) * 64;
    const int n0w  = (w >> 1) * 64;

    float acc[4][8][4];
#pragma unroll
    for (int mt = 0; mt < 4; mt++)
#pragma unroll
        for (int nt = 0; nt < 8; nt++)
#pragma unroll
            for (int j = 0; j < 4; j++) acc[mt][nt][j] = 0.f;

    const int chunk = tid & 7;
    const int rbase = tid >> 3;
    const int ccol  = chunk * 8;
    uint32_t sofs[8];
#pragma unroll
    for (int p = 0; p < 8; p++)
        sofs[p] = SWZ((uint32_t)((rbase + 16 * p) * 128 + chunk * 16));

    auto issue = [&](int kt, int st) {
        const uint32_t sb = smb + (uint32_t)st * OGSTAGE;
        const int col = kt * 64 + ccol;
#pragma unroll
        for (int p = 0; p < 8; p++) {
            size_t ga = (size_t)(bm * 128 + rbase + 16 * p) * E_DIM + col;
            size_t gb = (size_t)(bn * 128 + rbase + 16 * p) * E_DIM + col;
            CP_ASYNC16(sb + OG_A + sofs[p], Af + ga);
            CP_ASYNC16(sb + OG_B + sofs[p], Bf + gb);
        }
        CP_COMMIT();
    };

    issue(0, 0);

    const int a_r   = (lane & 7) + ((lane >> 3) & 1) * 8;
    const int a_c16 = lane >> 4;
    const int b_r   = (lane & 7) + ((lane >> 4) & 1) * 8;
    const int b_c16 = (lane >> 3) & 1;

    for (int kt = 0; kt < NKT; kt++) {
        CP_WAIT0();
        __syncthreads();
        const uint32_t sb = smb + (uint32_t)(kt & 1) * OGSTAGE;

        if (kt + 1 < NKT) issue(kt + 1, (kt + 1) & 1);

#pragma unroll
        for (int ks = 0; ks < 4; ks++) {
            uint32_t bf2[8][2];
#pragma unroll
            for (int ntp = 0; ntp < 4; ntp++) {
                int nrow = n0w + ntp * 16 + b_r;
                uint32_t off = SWZ((uint32_t)(nrow * 128 + ks * 32 + b_c16 * 16));
                LDMATRIX_X4(bf2[2 * ntp][0], bf2[2 * ntp][1],
                            bf2[2 * ntp + 1][0], bf2[2 * ntp + 1][1], sb + OG_B + off);
            }
#pragma unroll
            for (int mt = 0; mt < 4; mt++) {
                uint32_t af[4];
                int row = m0w + mt * 16 + a_r;
                uint32_t off = SWZ((uint32_t)(row * 128 + ks * 32 + a_c16 * 16));
                LDMATRIX_X4(af[0], af[1], af[2], af[3], sb + OG_A + off);
#pragma unroll
                for (int nt = 0; nt < 8; nt++)
                    MMA_F16(acc[mt][nt], af, bf2[nt]);
            }
        }
    }

#pragma unroll
    for (int mt = 0; mt < 4; mt++) {
        size_t m = (size_t)(bm * 128 + m0w + mt * 16 + (lane >> 2));
#pragma unroll
        for (int nt = 0; nt < 8; nt++) {
            size_t n = (size_t)(bn * 128 + n0w + nt * 8 + (lane & 3) * 2);
            float* p = Cf + m * E_DIM + n;
            *(float2*)p = make_float2(acc[mt][nt][0], acc[mt][nt][1]);
            *(float2*)(p + (size_t)8 * E_DIM) = make_float2(acc[mt][nt][2], acc[mt][nt][3]);
        }
    }
}

// ---------------------------------------------------------------------------
// Flash attention, all single fp16, 1-pass QK and 1-pass PV. (R12 version)
// Per CTA: 128 q rows of one (b,h), 128 threads, 4 warps x 32 q-rows.
// Q fragments in REGISTERS (loaded once). KV tile 64, 2-stage cp.async,
// one sync/iter. smem = 2 x (K 8KB + V 8KB) = 32KB -> 2 CTAs/SM.
// ---------------------------------------------------------------------------
#define A_K   0
#define A_V   8192
#define ASTAGE 16384
#define ATTN_SMEM (2 * ASTAGE)
#define NKV (SEQ / 64)   // 32
#define QBLK 128

__global__ __launch_bounds__(128, 2) void attn_mma(const float* __restrict__ qp)
{
    extern __shared__ __align__(1024) char sm[];
    const uint32_t smb = smem_to_u32(sm);
    const int tid  = threadIdx.x;
    const int wid  = tid >> 5;
    const int lane = tid & 31;
    const int bh   = blockIdx.y;
    const int b    = bh >> 4;
    const int h    = bh & 15;
    const int qbase = blockIdx.x * QBLK;
    const int wq0   = wid * 32;
    const float cq  = cosf(qp[0] + qp[1]);

    const size_t bS = (size_t)b * SEQ;
    const int h64 = h * 64;

    const __nv_bfloat16* kg = g_kf + bS * E_DIM + h64;
    const __nv_bfloat16* vg = g_vf + bS * E_DIM + h64;
    const int chunk = tid & 7;
    const int crow  = tid >> 3;
    const int ccol  = chunk * 8;
    uint32_t sco[4];
#pragma unroll
    for (int p = 0; p < 4; p++)
        sco[p] = SWZ((uint32_t)((crow + 16 * p) * 128 + chunk * 16));

    auto issue_stage = [&](int it, int st) {
        const uint32_t sb = smb + (uint32_t)st * ASTAGE;
#pragma unroll
        for (int p = 0; p < 4; p++) {
            const size_t r = (size_t)(it * 64 + crow + 16 * p) * E_DIM + ccol;
            CP_ASYNC16(sb + A_K + sco[p], kg + r);
            CP_ASYNC16(sb + A_V + sco[p], vg + r);
        }
        CP_COMMIT();
    };

    issue_stage(0, 0);

    // ---- Q fragments in registers (fp16, pre-scaled), held all loop ----
    unsigned qf[2][4][4];
    {
#pragma unroll
        for (int mt = 0; mt < 2; mt++) {
            const size_t base = (bS + qbase + wq0 + mt * 16 + (lane >> 2)) * E_DIM
                                + h64 + (lane & 3) * 2;
            const __nv_bfloat16* qp_ = g_qf + base;
#pragma unroll
            for (int ks = 0; ks < 4; ks++) {
                qf[mt][ks][0] = *(const unsigned*)(qp_ + ks * 16);
                qf[mt][ks][1] = *(const unsigned*)(qp_ + 8 * E_DIM + ks * 16);
                qf[mt][ks][2] = *(const unsigned*)(qp_ + ks * 16 + 8);
                qf[mt][ks][3] = *(const unsigned*)(qp_ + 8 * E_DIM + ks * 16 + 8);
            }
        }
    }

    float mx[2][2], lsum[2][2];
    float oacc[2][8][4];
#pragma unroll
    for (int mt = 0; mt < 2; mt++) {
        mx[mt][0] = -1e30f; mx[mt][1] = -1e30f;
        lsum[mt][0] = 0.f;  lsum[mt][1] = 0.f;
#pragma unroll
        for (int nt = 0; nt < 8; nt++)
#pragma unroll
            for (int j = 0; j < 4; j++) oacc[mt][nt][j] = 0.f;
    }

    const int brow  = (lane & 7) + ((lane >> 4) & 1) * 8;
    const int bc16  = (lane >> 3) & 1;
    const int vrow  = lane & 15;
    const int vcs   = (lane >> 4) * 16;

    for (int it = 0; it < NKV; it++) {
        CP_WAIT0();
        __syncthreads();

        const uint32_t sb = smb + (uint32_t)(it & 1) * ASTAGE;

        if (it + 1 < NKV) issue_stage(it + 1, (it + 1) & 1);

        // ---- S = Q.K^T ----
        float sacc[2][8][4];
#pragma unroll
        for (int mt = 0; mt < 2; mt++)
#pragma unroll
            for (int nt = 0; nt < 8; nt++)
#pragma unroll
                for (int j = 0; j < 4; j++) sacc[mt][nt][j] = 0.f;

#pragma unroll
        for (int ks = 0; ks < 4; ks++) {
            unsigned kf2[8][2];
#pragma unroll
            for (int ntp = 0; ntp < 4; ntp++) {
                uint32_t off = SWZ((uint32_t)((ntp * 16 + brow) * 128 + ks * 32 + bc16 * 16));
                LDMATRIX_X4(kf2[2 * ntp][0], kf2[2 * ntp][1],
                            kf2[2 * ntp + 1][0], kf2[2 * ntp + 1][1], sb + A_K + off);
            }
#pragma unroll
            for (int mt = 0; mt < 2; mt++)
#pragma unroll
                for (int nt = 0; nt < 8; nt++)
                    MMA_F16(sacc[mt][nt], qf[mt][ks], kf2[nt]);
        }

        // ---- online softmax per m-tile ----
#pragma unroll
        for (int mt = 0; mt < 2; mt++) {
            float mn0 = mx[mt][0], mn1 = mx[mt][1];
#pragma unroll
            for (int nt = 0; nt < 8; nt++) {
                mn0 = fmaxf(mn0, fmaxf(sacc[mt][nt][0], sacc[mt][nt][1]));
                mn1 = fmaxf(mn1, fmaxf(sacc[mt][nt][2], sacc[mt][nt][3]));
            }
            mn0 = fmaxf(mn0, __shfl_xor_sync(0xffffffffu, mn0, 1));
            mn0 = fmaxf(mn0, __shfl_xor_sync(0xffffffffu, mn0, 2));
            mn1 = fmaxf(mn1, __shfl_xor_sync(0xffffffffu, mn1, 1));
            mn1 = fmaxf(mn1, __shfl_xor_sync(0xffffffffu, mn1, 2));
            float sc0 = __expf(mx[mt][0] - mn0);
            float sc1 = __expf(mx[mt][1] - mn1);
            mx[mt][0] = mn0; mx[mt][1] = mn1;
            float rs0 = 0.f, rs1 = 0.f;
#pragma unroll
            for (int nt = 0; nt < 8; nt++) {
                sacc[mt][nt][0] = __expf(sacc[mt][nt][0] - mn0); rs0 += sacc[mt][nt][0];
                sacc[mt][nt][1] = __expf(sacc[mt][nt][1] - mn0); rs0 += sacc[mt][nt][1];
                sacc[mt][nt][2] = __expf(sacc[mt][nt][2] - mn1); rs1 += sacc[mt][nt][2];
                sacc[mt][nt][3] = __expf(sacc[mt][nt][3] - mn1); rs1 += sacc[mt][nt][3];
            }
            rs0 += __shfl_xor_sync(0xffffffffu, rs0, 1);
            rs0 += __shfl_xor_sync(0xffffffffu, rs0, 2);
            rs1 += __shfl_xor_sync(0xffffffffu, rs1, 1);
            rs1 += __shfl_xor_sync(0xffffffffu, rs1, 2);
            lsum[mt][0] = lsum[mt][0] * sc0 + rs0;
            lsum[mt][1] = lsum[mt][1] * sc1 + rs1;
#pragma unroll
            for (int nt = 0; nt < 8; nt++) {
                oacc[mt][nt][0] *= sc0; oacc[mt][nt][1] *= sc0;
                oacc[mt][nt][2] *= sc1; oacc[mt][nt][3] *= sc1;
            }
        }

        // ---- O += P.V ----
#pragma unroll
        for (int j = 0; j < 4; j++) {
            unsigned vf2[8][2];
#pragma unroll
            for (int dp = 0; dp < 4; dp++) {
                uint32_t off = SWZ((uint32_t)((j * 16 + vrow) * 128 + dp * 32 + vcs));
                LDMATRIX_X4_T(vf2[2 * dp][0], vf2[2 * dp][1],
                              vf2[2 * dp + 1][0], vf2[2 * dp + 1][1], sb + A_V + off);
            }
#pragma unroll
            for (int mt = 0; mt < 2; mt++) {
                unsigned ph[4];
                ph[0] = pack_f16(sacc[mt][2 * j][0],     sacc[mt][2 * j][1]);
                ph[1] = pack_f16(sacc[mt][2 * j][2],     sacc[mt][2 * j][3]);
                ph[2] = pack_f16(sacc[mt][2 * j + 1][0], sacc[mt][2 * j + 1][1]);
                ph[3] = pack_f16(sacc[mt][2 * j + 1][2], sacc[mt][2 * j + 1][3]);
#pragma unroll
                for (int nt = 0; nt < 8; nt++)
                    MMA_F16(oacc[mt][nt], ph, vf2[nt]);
            }
        }
    }

    // ---- epilogue: normalize, +c on dk<4, write fp16 mix ----
    const bool adds = ((lane & 3) < 2);
#pragma unroll
    for (int mt = 0; mt < 2; mt++) {
        const float inv0 = 1.f / lsum[mt][0];
        const float inv1 = 1.f / lsum[mt][1];
        const size_t row0 = (bS + qbase + wq0 + mt * 16 + (lane >> 2)) * E_DIM
                            + h64 + (lane & 3) * 2;
        const size_t row1 = row0 + 8 * E_DIM;
#pragma unroll
        for (int nt = 0; nt < 8; nt++) {
            const float add = (nt == 0 && adds) ? cq : 0.f;
            *(unsigned*)(g_mf + row0 + nt * 8) =
                pack_f16(oacc[mt][nt][0] * inv0 + add, oacc[mt][nt][1] * inv0 + add);
            *(unsigned*)(g_mf + row1 + nt * 8) =
                pack_f16(oacc[mt][nt][2] * inv1 + add, oacc[mt][nt][3] * inv1 + add);
        }
    }
}

// ---------------------------------------------------------------------------
extern "C" void kernel_launch(void* const* d_in, const int* in_sizes, int n_in,
                              void* d_out, int out_size)
{
    const float* x  = (const float*)d_in[0];
    const float* Wq = (const float*)d_in[1];
    const float* Wk = (const float*)d_in[2];
    const float* Wv = (const float*)d_in[3];
    const float* Wo = (const float*)d_in[4];
    const float* qp = (const float*)d_in[5];
    float* out = (float*)d_out;

    cudaFuncSetAttribute(qkv_gemm_mma, cudaFuncAttributeMaxDynamicSharedMemorySize, QG_SMEM);
    cudaFuncSetAttribute(out_gemm_mma, cudaFuncAttributeMaxDynamicSharedMemorySize, OG_SMEM);
    cudaFuncSetAttribute(attn_mma,     cudaFuncAttributeMaxDynamicSharedMemorySize, ATTN_SMEM);

    prep_all<<<(NPREP4 + 511) / 512, 256>>>(x, Wq, Wk, Wv, Wo);

    qkv_gemm_mma<<<dim3(16, 32, 3), 128, QG_SMEM>>>();
    attn_mma<<<dim3(SEQ / QBLK, BATCH * NHEAD), 128, ATTN_SMEM>>>(qp);
    out_gemm_mma<<<dim3(8, 32), 128, OG_SMEM>>>(out);
}